// round 1
// baseline (speedup 1.0000x reference)
#include <cuda_runtime.h>
#include <cstdint>

#define Bx 8
#define Dx 128
#define Tx 4096
#define Kx 1024
#define Sx 8
#define ROWS (Bx*Tx)            // 32768
#define BLK_M 128
#define BLK_N 128
#define NTILES (Kx/BLK_N)       // 8
#define GRID_STAGE (ROWS/BLK_M) // 256

// scratch (device-global; no runtime allocation allowed)
__device__ float g_R[(size_t)ROWS * Dx];       // residual, row-major (row, d)
__device__ float g_Q[(size_t)ROWS * Dx];       // accumulated quantized
__device__ float g_c2[Sx * Kx];                // ||codeword||^2 per stage
__device__ int   g_codes[Sx * ROWS];           // argmin indices
__device__ float g_part[Sx * GRID_STAGE];      // per-CTA commit partial sums

// ---------------------------------------------------------------------------
// Transpose x (B, D, T) -> R (B*T, D); zero Q.
// ---------------------------------------------------------------------------
__global__ void prep_transpose(const float* __restrict__ x) {
    __shared__ float tile[32][33];
    int b  = blockIdx.z;
    int d0 = blockIdx.y * 32;
    int t0 = blockIdx.x * 32;
    int lx = threadIdx.x, ly = threadIdx.y;   // 32 x 8
    #pragma unroll
    for (int yy = ly; yy < 32; yy += 8)
        tile[yy][lx] = x[((size_t)b * Dx + d0 + yy) * Tx + t0 + lx];
    __syncthreads();
    #pragma unroll
    for (int yy = ly; yy < 32; yy += 8) {
        size_t off = ((size_t)b * Tx + t0 + yy) * Dx + d0 + lx;
        g_R[off] = tile[lx][yy];
        g_Q[off] = 0.0f;
    }
}

// ---------------------------------------------------------------------------
// ||c||^2 for all stages: one warp per codeword.
// ---------------------------------------------------------------------------
__global__ void c2_kernel(const float* __restrict__ cb) {
    int w    = (blockIdx.x * blockDim.x + threadIdx.x) >> 5;
    int lane = threadIdx.x & 31;
    if (w >= Sx * Kx) return;
    float4 v = reinterpret_cast<const float4*>(cb)[(size_t)w * 32 + lane];
    float p = v.x * v.x + v.y * v.y + v.z * v.z + v.w * v.w;
    #pragma unroll
    for (int o = 16; o; o >>= 1) p += __shfl_down_sync(0xFFFFFFFFu, p, o);
    if (lane == 0) g_c2[w] = p;
}

// ---------------------------------------------------------------------------
// One RVQ stage: scores = R @ C^T (128x1024x128 per CTA-tile), online argmin of
// (||c||^2 - 2*score), then gather + residual/qout update + commit partial.
// ---------------------------------------------------------------------------
__global__ void __launch_bounds__(256) stage_kernel(const float* __restrict__ cb_all, int s) {
    extern __shared__ float sm[];
    float* As   = sm;                       // [128][132]  (d-major, padded)
    float* Bs   = As + 128 * 132;           // [16][132]
    float* redv = Bs + 16 * 132;            // [2048]
    int*   redi = (int*)(redv + 2048);      // [2048]
    int*   bidx = redi + 2048;              // [128]

    const float* cb = cb_all + (size_t)s * Kx * Dx;
    const int row0 = blockIdx.x * BLK_M;
    const int tid  = threadIdx.x;
    const int tx   = tid & 15;
    const int ty   = tid >> 4;

    // ---- load residual tile into smem, transposed to [d][m] ----
    const float4* R4 = reinterpret_cast<const float4*>(g_R + (size_t)row0 * Dx);
    #pragma unroll
    for (int it = 0; it < (BLK_M * Dx / 4) / 256; it++) {
        int idx = it * 256 + tid;
        int m  = idx >> 5;          // 32 float4 per row
        int d4 = idx & 31;
        float4 v = R4[(size_t)m * 32 + d4];
        As[(d4 * 4 + 0) * 132 + m] = v.x;
        As[(d4 * 4 + 1) * 132 + m] = v.y;
        As[(d4 * 4 + 2) * 132 + m] = v.z;
        As[(d4 * 4 + 3) * 132 + m] = v.w;
    }

    float minv[8];
    int   mini[8];
    #pragma unroll
    for (int i = 0; i < 8; i++) { minv[i] = __int_as_float(0x7F800000); mini[i] = 0; }

    for (int nt = 0; nt < NTILES; nt++) {
        const int n0 = nt * BLK_N;
        float acc[8][8];
        #pragma unroll
        for (int i = 0; i < 8; i++)
            #pragma unroll
            for (int j = 0; j < 8; j++) acc[i][j] = 0.0f;

        for (int kk = 0; kk < Dx / 16; kk++) {
            __syncthreads();   // Bs (and first-iter As) safe to (re)write / first read
            // load codebook chunk [BLK_N][16] -> Bs[d][n]
            #pragma unroll
            for (int it = 0; it < (BLK_N * 16 / 4) / 256; it++) {
                int idx = it * 256 + tid;
                int n  = idx >> 2;
                int d4 = idx & 3;
                float4 v = *reinterpret_cast<const float4*>(
                    cb + (size_t)(n0 + n) * Dx + kk * 16 + d4 * 4);
                Bs[(d4 * 4 + 0) * 132 + n] = v.x;
                Bs[(d4 * 4 + 1) * 132 + n] = v.y;
                Bs[(d4 * 4 + 2) * 132 + n] = v.z;
                Bs[(d4 * 4 + 3) * 132 + n] = v.w;
            }
            __syncthreads();
            #pragma unroll
            for (int k = 0; k < 16; k++) {
                int dd = kk * 16 + k;
                float4 a0 = *reinterpret_cast<const float4*>(&As[dd * 132 + ty * 8]);
                float4 a1 = *reinterpret_cast<const float4*>(&As[dd * 132 + ty * 8 + 4]);
                float4 b0 = *reinterpret_cast<const float4*>(&Bs[k  * 132 + tx * 8]);
                float4 b1 = *reinterpret_cast<const float4*>(&Bs[k  * 132 + tx * 8 + 4]);
                float a[8] = {a0.x, a0.y, a0.z, a0.w, a1.x, a1.y, a1.z, a1.w};
                float b[8] = {b0.x, b0.y, b0.z, b0.w, b1.x, b1.y, b1.z, b1.w};
                #pragma unroll
                for (int i = 0; i < 8; i++)
                    #pragma unroll
                    for (int j = 0; j < 8; j++)
                        acc[i][j] = fmaf(a[i], b[j], acc[i][j]);
            }
        }

        // ---- online argmin of (c2 - 2*score); k ascending => strict '<' keeps first ----
        #pragma unroll
        for (int j = 0; j < 8; j++) {
            int gk = n0 + tx * 8 + j;
            float c2 = g_c2[s * Kx + gk];
            #pragma unroll
            for (int i = 0; i < 8; i++) {
                float v = fmaf(-2.0f, acc[i][j], c2);
                if (v < minv[i]) { minv[i] = v; mini[i] = gk; }
            }
        }
    }

    // ---- cross-thread argmin reduction per row (tie -> smaller index) ----
    __syncthreads();
    #pragma unroll
    for (int i = 0; i < 8; i++) {
        redv[(ty * 8 + i) * 16 + tx] = minv[i];
        redi[(ty * 8 + i) * 16 + tx] = mini[i];
    }
    __syncthreads();
    if (tid < BLK_M) {
        float bv = redv[tid * 16];
        int   bi = redi[tid * 16];
        #pragma unroll
        for (int t = 1; t < 16; t++) {
            float v = redv[tid * 16 + t];
            int   ix = redi[tid * 16 + t];
            if (v < bv || (v == bv && ix < bi)) { bv = v; bi = ix; }
        }
        bidx[tid] = bi;
        g_codes[s * ROWS + row0 + tid] = bi;
    }
    __syncthreads();

    // ---- gather chosen codeword, update residual & qout, commit partial ----
    float commit = 0.0f;
    #pragma unroll
    for (int it = 0; it < (BLK_M * Dx) / 256; it++) {
        int idx = it * 256 + tid;
        int m = idx >> 7;
        int d = idx & 127;
        int k = bidx[m];
        float q = cb[(size_t)k * Dx + d];
        size_t off = (size_t)(row0 + m) * Dx + d;
        float r = g_R[off];
        float df = q - r;
        commit = fmaf(df, df, commit);
        g_R[off] = r - q;
        g_Q[off] += q;
    }
    __syncthreads();           // redv free for reuse
    redv[tid] = commit;
    __syncthreads();
    #pragma unroll
    for (int st = 128; st > 0; st >>= 1) {
        if (tid < st) redv[tid] += redv[tid + st];
        __syncthreads();
    }
    if (tid == 0) g_part[s * GRID_STAGE + blockIdx.x] = redv[0];
}

// ---------------------------------------------------------------------------
// Q (B*T, D) -> out quantized (B, D, T)
// ---------------------------------------------------------------------------
__global__ void finish_transpose(float* __restrict__ out) {
    __shared__ float tile[32][33];
    int b  = blockIdx.z;
    int d0 = blockIdx.y * 32;
    int t0 = blockIdx.x * 32;
    int lx = threadIdx.x, ly = threadIdx.y;
    #pragma unroll
    for (int yy = ly; yy < 32; yy += 8)
        tile[yy][lx] = g_Q[((size_t)b * Tx + t0 + yy) * Dx + d0 + lx];
    __syncthreads();
    #pragma unroll
    for (int yy = ly; yy < 32; yy += 8)
        out[((size_t)b * Dx + d0 + yy) * Tx + t0 + lx] = tile[lx][yy];
}

// ---------------------------------------------------------------------------
// codes -> float, bw, penalty
// ---------------------------------------------------------------------------
__global__ void pack_kernel(float* __restrict__ out) {
    const size_t QOFF = (size_t)Bx * Dx * Tx;       // 4,194,304
    const size_t COFF = QOFF + (size_t)Sx * ROWS;   // + 262,144
    int i = blockIdx.x * 256 + threadIdx.x;
    if (i < Sx * ROWS) out[QOFF + i] = (float)g_codes[i];
    if (i == 0) {
        float ssum = 0.0f;
        for (int j = 0; j < Sx * GRID_STAGE; j++) ssum += g_part[j];
        out[COFF + 0] = 6000.0f;                                    // 8 * log2(1024) * 75
        out[COFF + 1] = ssum / ((float)Sx * (float)ROWS * (float)Dx);
    }
}

extern "C" void kernel_launch(void* const* d_in, const int* in_sizes, int n_in,
                              void* d_out, int out_size) {
    const float* x  = (const float*)d_in[0];
    const float* cb = (const float*)d_in[1];
    float* out = (float*)d_out;

    const int SMEM_BYTES = (128 * 132 + 16 * 132 + 2048 + 2048 + 128) * 4; // 92,928 B
    cudaFuncSetAttribute(stage_kernel, cudaFuncAttributeMaxDynamicSharedMemorySize, SMEM_BYTES);

    prep_transpose<<<dim3(Tx / 32, Dx / 32, Bx), dim3(32, 8)>>>(x);
    c2_kernel<<<(Sx * Kx * 32) / 256, 256>>>(cb);
    for (int s = 0; s < Sx; s++)
        stage_kernel<<<GRID_STAGE, 256, SMEM_BYTES>>>(cb, s);
    finish_transpose<<<dim3(Tx / 32, Dx / 32, Bx), dim3(32, 8)>>>(out);
    pack_kernel<<<(Sx * ROWS + 255) / 256, 256>>>(out);
}